// round 4
// baseline (speedup 1.0000x reference)
#include <cuda_runtime.h>
#include <stdint.h>

#define SRC_SIZE 262144
#define DST_SIZE 65536
#define N_EDGES  2097152
#define BATCH    4
#define FEAT     32

#define SCAN_BLOCKS 256
#define SCAN_CHUNK  256   // DST_SIZE / SCAN_BLOCKS

#define FIX_SCALE 16777216.0f       // 2^24
#define INV_FIX   (1.0f / 16777216.0f)

// ---------------------------------------------------------------------------
// Scratch
// ---------------------------------------------------------------------------
__device__ unsigned long long g_hist[DST_SIZE];   // {count:u32 | fixed24(sum w):u32}
__device__ float          g_inv[DST_SIZE];        // 1/(norm+1e-8)
__device__ int            g_offsets[DST_SIZE + 1];
__device__ unsigned short g_rank[N_EDGES];        // edge's arrival rank within its dst
__device__ int2           g_sorted[N_EDGES];      // {src, __float_as_int(w)}

// ---------------------------------------------------------------------------
// K1: histogram; the returned old count is this edge's rank within its dst.
// ---------------------------------------------------------------------------
__global__ void k_hist(const float* __restrict__ weights,
                       const int* __restrict__ dst_idx, int n_edges) {
    int e = blockIdx.x * blockDim.x + threadIdx.x;
    if (e < n_edges) {
        int d = __ldg(&dst_idx[e]);
        float w = __ldg(&weights[e]);
        unsigned long long v =
            (1ULL << 32) | (unsigned long long)(unsigned int)(w * FIX_SCALE);
        unsigned long long old = atomicAdd(&g_hist[d], v);
        g_rank[e] = (unsigned short)(old >> 32);
    }
}

// ---------------------------------------------------------------------------
// K2: merged scan. Each block (a) strided-reduces counts of all preceding
// blocks' counters to get its global prefix, (b) scans its own 256 counters,
// emitting offsets and inv_norm.
// ---------------------------------------------------------------------------
__global__ void k_scan() {
    __shared__ int sh[8];
    __shared__ int shp[8];
    __shared__ int s_prefix;

    const int t = threadIdx.x;
    const int lane = t & 31;
    const int warp = t >> 5;
    const int nprev = blockIdx.x * SCAN_CHUNK;   // counters before this block

    // (a) prefix over preceding counters, 4 independent partial sums for MLP
    int p0 = 0, p1 = 0, p2 = 0, p3 = 0;
    int i = t;
    for (; i + 768 < nprev; i += 1024) {
        p0 += (int)(g_hist[i]       >> 32);
        p1 += (int)(g_hist[i + 256] >> 32);
        p2 += (int)(g_hist[i + 512] >> 32);
        p3 += (int)(g_hist[i + 768] >> 32);
    }
    for (; i < nprev; i += 256) p0 += (int)(g_hist[i] >> 32);
    int p = (p0 + p1) + (p2 + p3);
#pragma unroll
    for (int off = 16; off > 0; off >>= 1)
        p += __shfl_down_sync(0xFFFFFFFFu, p, off);
    if (lane == 0) shp[warp] = p;
    __syncthreads();
    if (t == 0) {
        int acc = 0;
#pragma unroll
        for (int k = 0; k < 8; k++) acc += shp[k];
        s_prefix = acc;
    }

    // (b) inclusive scan of this block's 256 counters
    const int d = nprev + t;
    unsigned long long h = g_hist[d];
    int c = (int)(h >> 32);
    float norm = (float)(unsigned int)(h & 0xFFFFFFFFULL) * INV_FIX;

    int v = c;
#pragma unroll
    for (int off = 1; off < 32; off <<= 1) {
        int n = __shfl_up_sync(0xFFFFFFFFu, v, off);
        if (lane >= off) v += n;
    }
    if (lane == 31) sh[warp] = v;
    __syncthreads();
    if (warp == 0) {
        int u = (lane < 8) ? sh[lane] : 0;
#pragma unroll
        for (int off = 1; off < 8; off <<= 1) {
            int n = __shfl_up_sync(0xFFFFFFFFu, u, off);
            if (lane >= off) u += n;
        }
        if (lane < 8) sh[lane] = u;
    }
    __syncthreads();
    int incl = v + ((warp > 0) ? sh[warp - 1] : 0);

    int off = s_prefix + incl - c;
    g_offsets[d] = off;
    g_inv[d] = 1.0f / (norm + 1e-8f);
    if (d == DST_SIZE - 1) g_offsets[DST_SIZE] = off + c;
}

// ---------------------------------------------------------------------------
// K3: atomic-free scatter: pos = offsets[dst] + rank[edge]
// ---------------------------------------------------------------------------
__global__ void k_scatter(const float* __restrict__ weights,
                          const int* __restrict__ src_idx,
                          const int* __restrict__ dst_idx, int n_edges) {
    int e = blockIdx.x * blockDim.x + threadIdx.x;
    if (e < n_edges) {
        int d = __ldg(&dst_idx[e]);
        int pos = __ldg(&g_offsets[d]) + (int)g_rank[e];
        int2 p;
        p.x = __ldg(&src_idx[e]);
        p.y = __float_as_int(__ldg(&weights[e]));
        g_sorted[pos] = p;
    }
}

// ---------------------------------------------------------------------------
// K4: atomic-free segmented reduction. One warp per dst.
// lane: b = lane>>3 (batch), fg = lane&7 (float4 group). Unroll 8, dual accum.
// ---------------------------------------------------------------------------
__global__ void __launch_bounds__(256)
k_reduce(const float* __restrict__ x, float* __restrict__ out) {
    const int dst = (blockIdx.x * blockDim.x + threadIdx.x) >> 5;
    if (dst >= DST_SIZE) return;
    const int lane = threadIdx.x & 31;
    const int b  = lane >> 3;
    const int fg = lane & 7;

    const int beg = g_offsets[dst];
    const int end = g_offsets[dst + 1];

    const float* xb = x + (size_t)b * (SRC_SIZE * FEAT) + fg * 4;

    float ax = 0.f, ay = 0.f, az = 0.f, aw = 0.f;   // accum set A
    float bx = 0.f, by = 0.f, bz = 0.f, bw = 0.f;   // accum set B

    int j = beg;
    for (; j + 7 < end; j += 8) {
        int2 p0 = g_sorted[j];
        int2 p1 = g_sorted[j + 1];
        int2 p2 = g_sorted[j + 2];
        int2 p3 = g_sorted[j + 3];
        int2 p4 = g_sorted[j + 4];
        int2 p5 = g_sorted[j + 5];
        int2 p6 = g_sorted[j + 6];
        int2 p7 = g_sorted[j + 7];
        float4 v0 = *(const float4*)(xb + (size_t)p0.x * FEAT);
        float4 v1 = *(const float4*)(xb + (size_t)p1.x * FEAT);
        float4 v2 = *(const float4*)(xb + (size_t)p2.x * FEAT);
        float4 v3 = *(const float4*)(xb + (size_t)p3.x * FEAT);
        float4 v4 = *(const float4*)(xb + (size_t)p4.x * FEAT);
        float4 v5 = *(const float4*)(xb + (size_t)p5.x * FEAT);
        float4 v6 = *(const float4*)(xb + (size_t)p6.x * FEAT);
        float4 v7 = *(const float4*)(xb + (size_t)p7.x * FEAT);
        float w0 = __int_as_float(p0.y), w1 = __int_as_float(p1.y);
        float w2 = __int_as_float(p2.y), w3 = __int_as_float(p3.y);
        float w4 = __int_as_float(p4.y), w5 = __int_as_float(p5.y);
        float w6 = __int_as_float(p6.y), w7 = __int_as_float(p7.y);
        ax += w0 * v0.x; ay += w0 * v0.y; az += w0 * v0.z; aw += w0 * v0.w;
        bx += w1 * v1.x; by += w1 * v1.y; bz += w1 * v1.z; bw += w1 * v1.w;
        ax += w2 * v2.x; ay += w2 * v2.y; az += w2 * v2.z; aw += w2 * v2.w;
        bx += w3 * v3.x; by += w3 * v3.y; bz += w3 * v3.z; bw += w3 * v3.w;
        ax += w4 * v4.x; ay += w4 * v4.y; az += w4 * v4.z; aw += w4 * v4.w;
        bx += w5 * v5.x; by += w5 * v5.y; bz += w5 * v5.z; bw += w5 * v5.w;
        ax += w6 * v6.x; ay += w6 * v6.y; az += w6 * v6.z; aw += w6 * v6.w;
        bx += w7 * v7.x; by += w7 * v7.y; bz += w7 * v7.z; bw += w7 * v7.w;
    }
    for (; j + 1 < end; j += 2) {
        int2 p0 = g_sorted[j];
        int2 p1 = g_sorted[j + 1];
        float4 v0 = *(const float4*)(xb + (size_t)p0.x * FEAT);
        float4 v1 = *(const float4*)(xb + (size_t)p1.x * FEAT);
        float w0 = __int_as_float(p0.y), w1 = __int_as_float(p1.y);
        ax += w0 * v0.x; ay += w0 * v0.y; az += w0 * v0.z; aw += w0 * v0.w;
        bx += w1 * v1.x; by += w1 * v1.y; bz += w1 * v1.z; bw += w1 * v1.w;
    }
    if (j < end) {
        int2 p0 = g_sorted[j];
        float4 v0 = *(const float4*)(xb + (size_t)p0.x * FEAT);
        float w0 = __int_as_float(p0.y);
        ax += w0 * v0.x; ay += w0 * v0.y; az += w0 * v0.z; aw += w0 * v0.w;
    }

    const float inv = g_inv[dst];
    float4 r = make_float4((ax + bx) * inv, (ay + by) * inv,
                           (az + bz) * inv, (aw + bw) * inv);
    float* o = out + (size_t)b * (DST_SIZE * FEAT) + (size_t)dst * FEAT + fg * 4;
    *(float4*)o = r;
}

// ---------------------------------------------------------------------------
// kernel_launch
// ---------------------------------------------------------------------------
extern "C" void kernel_launch(void* const* d_in, const int* in_sizes, int n_in,
                              void* d_out, int out_size) {
    const float* x       = (const float*)d_in[0];
    const float* weights = (const float*)d_in[1];
    const int*   src_idx = (const int*)d_in[2];
    const int*   dst_idx = (const int*)d_in[3];
    float*       out     = (float*)d_out;
    const int n_edges = in_sizes[1];

    // Zero the packed histogram via a memset node (graph-capturable, no alloc).
    void* hist_ptr = nullptr;
    cudaGetSymbolAddress(&hist_ptr, g_hist);
    cudaMemsetAsync(hist_ptr, 0, DST_SIZE * sizeof(unsigned long long), 0);

    k_hist<<<(n_edges + 255) / 256, 256>>>(weights, dst_idx, n_edges);
    k_scan<<<SCAN_BLOCKS, SCAN_CHUNK>>>();
    k_scatter<<<(n_edges + 255) / 256, 256>>>(weights, src_idx, dst_idx, n_edges);
    k_reduce<<<DST_SIZE / 8, 256>>>(x, out);
}